// round 2
// baseline (speedup 1.0000x reference)
#include <cuda_runtime.h>
#include <math.h>

// ---------------------------------------------------------------------------
// BiBoMoE layer, GB300 baseline (fp32 SIMT GEMMs, sparse expert dispatch)
//   B=4 S=4096 H=1024 I=512 E=16 TOPK=2 KS=3   T=16384 tokens
// ---------------------------------------------------------------------------

#define B_  4
#define S_  4096
#define H_  1024
#define I_  512
#define E_  16
#define KS_ 3
#define T_  (B_ * S_)          // 16384
#define NROUTED 15             // experts 0..14 are SwiGLU, 15 is identity

#define BM 128
#define BN 64
#define BK 16
#define PMAX   34816           // 2T + 16*BM slack, multiple of BM
#define NTILES (PMAX / BM)     // 272

// ------------------------- device scratch (static) -------------------------
__device__ __align__(16) float g_hbuf[PMAX * I_];       // routed silu(g)*u, per pair-slot
__device__ __align__(16) float g_shbuf[T_ * I_];        // shared silu(gate)*up
__device__ __align__(16) float g_convT[KS_ * H_ * I_];  // conv_w transposed to [k][h][i]
__device__ int   g_tok[PMAX];      // pair-slot -> token
__device__ float g_wt[PMAX];       // pair-slot -> combine weight
__device__ int   g_cnt[E_];
__device__ int   g_cur[E_];
__device__ int   g_segend[E_];
__device__ int   g_tileexp[NTILES];
__device__ int   g_top_e[T_ * 2];
__device__ float g_top_w[T_ * 2];

// ------------------------------ tiny kernels -------------------------------
// conv_w (I,H,KS) -> g_convT [k][h][i]; also zero the per-expert counters
__global__ void k_prep_conv(const float* __restrict__ cw) {
    int idx = blockIdx.x * blockDim.x + threadIdx.x;
    if (idx < E_) g_cnt[idx] = 0;
    if (idx >= KS_ * H_ * I_) return;
    int i = idx % I_;
    int h = (idx / I_) % H_;
    int k = idx / (I_ * H_);
    g_convT[idx] = cw[(size_t)i * (H_ * KS_) + h * KS_ + k];
}

// one warp per token: logits -> softmax -> top2 -> counts + identity-expert init of out
__global__ void k_router(const float* __restrict__ x, const float* __restrict__ rw,
                         const float* __restrict__ rb, float* __restrict__ out) {
    int gw   = (blockIdx.x * blockDim.x + threadIdx.x) >> 5;
    int lane = threadIdx.x & 31;
    if (gw >= T_) return;
    const float* xt = x + (size_t)gw * H_;

    float acc[E_];
#pragma unroll
    for (int e = 0; e < E_; e++) acc[e] = 0.f;

    for (int j = 0; j < H_ / 32; j++) {
        int h = j * 32 + lane;
        float xv = xt[h];
        const float* wr = rw + (size_t)h * E_;
        float4 w0 = *(const float4*)(wr);
        float4 w1 = *(const float4*)(wr + 4);
        float4 w2 = *(const float4*)(wr + 8);
        float4 w3 = *(const float4*)(wr + 12);
        acc[0]  = fmaf(xv, w0.x, acc[0]);  acc[1]  = fmaf(xv, w0.y, acc[1]);
        acc[2]  = fmaf(xv, w0.z, acc[2]);  acc[3]  = fmaf(xv, w0.w, acc[3]);
        acc[4]  = fmaf(xv, w1.x, acc[4]);  acc[5]  = fmaf(xv, w1.y, acc[5]);
        acc[6]  = fmaf(xv, w1.z, acc[6]);  acc[7]  = fmaf(xv, w1.w, acc[7]);
        acc[8]  = fmaf(xv, w2.x, acc[8]);  acc[9]  = fmaf(xv, w2.y, acc[9]);
        acc[10] = fmaf(xv, w2.z, acc[10]); acc[11] = fmaf(xv, w2.w, acc[11]);
        acc[12] = fmaf(xv, w3.x, acc[12]); acc[13] = fmaf(xv, w3.y, acc[13]);
        acc[14] = fmaf(xv, w3.z, acc[14]); acc[15] = fmaf(xv, w3.w, acc[15]);
    }
#pragma unroll
    for (int e = 0; e < E_; e++) {
#pragma unroll
        for (int off = 16; off > 0; off >>= 1)
            acc[e] += __shfl_xor_sync(0xffffffffu, acc[e], off);
    }
#pragma unroll
    for (int e = 0; e < E_; e++) acc[e] += rb[e];

    float mx = acc[0];
#pragma unroll
    for (int e = 1; e < E_; e++) mx = fmaxf(mx, acc[e]);
    float p[E_], S = 0.f;
#pragma unroll
    for (int e = 0; e < E_; e++) { p[e] = expf(acc[e] - mx); S += p[e]; }

    int i1 = 0;
#pragma unroll
    for (int e = 1; e < E_; e++) if (p[e] > p[i1]) i1 = e;   // first max on ties (jax)
    int i2 = (i1 == 0) ? 1 : 0;
#pragma unroll
    for (int e = 0; e < E_; e++) if (e != i1 && p[e] > p[i2]) i2 = e;

    float invS = 1.f / S;
    float w1 = p[i1] * invS, w2 = p[i2] * invS;
    float inv = 1.f / (w1 + w2 + 1e-6f);
    float nw1 = w1 * inv, nw2 = w2 * inv;
    float wid = (i1 == E_ - 1) ? nw1 : ((i2 == E_ - 1) ? nw2 : 0.f);

    if (lane == 0) {
        g_top_e[2 * gw]     = i1; g_top_w[2 * gw]     = nw1;
        g_top_e[2 * gw + 1] = i2; g_top_w[2 * gw + 1] = nw2;
        if (i1 < NROUTED) atomicAdd(&g_cnt[i1], 1);
        if (i2 < NROUTED) atomicAdd(&g_cnt[i2], 1);
    }
    // identity-expert contribution initializes out (out is poisoned pre-run)
    float* ot = out + (size_t)gw * H_;
    for (int j = 0; j < H_ / 32; j++) {
        int h = j * 32 + lane;
        ot[h] = wid * xt[h];
    }
}

// single thread: BM-aligned segment offsets + tile->expert map
__global__ void k_offsets() {
    if (threadIdx.x != 0 || blockIdx.x != 0) return;
    for (int tt = 0; tt < NTILES; tt++) g_tileexp[tt] = -1;
    int o = 0;
    for (int e = 0; e < NROUTED; e++) {
        g_cur[e]    = o;
        g_segend[e] = o + g_cnt[e];
        int nt = (g_cnt[e] + BM - 1) / BM;
        for (int tt = 0; tt < nt; tt++) {
            int ti = o / BM + tt;
            if (ti < NTILES) g_tileexp[ti] = e;
        }
        o += nt * BM;
    }
}

__global__ void k_scatter() {
    int t = blockIdx.x * blockDim.x + threadIdx.x;
    if (t >= T_) return;
    for (int pqi = 0; pqi < 2; pqi++) {
        int e = g_top_e[2 * t + pqi];
        if (e < NROUTED) {
            int pos = atomicAdd(&g_cur[e], 1);
            g_tok[pos] = t;
            g_wt[pos]  = g_top_w[2 * t + pqi];
        }
    }
}

// ---------------------- K2: routed gate+up (gather, dual-B) ----------------
// hbuf[r, :] = silu(x[tok[r]] @ Wg[e]) * (x[tok[r]] @ Wu[e])
__global__ __launch_bounds__(256) void k2_gateup(const float* __restrict__ x,
                                                 const float* __restrict__ wg,
                                                 const float* __restrict__ wu) {
    int e = g_tileexp[blockIdx.x];
    if (e < 0) return;
    int rbase  = blockIdx.x * BM;
    int nb     = blockIdx.y * BN;
    int segend = g_segend[e];
    const float* wgp = wg + (size_t)e * H_ * I_;
    const float* wup = wu + (size_t)e * H_ * I_;

    __shared__ __align__(16) float As[BK][BM + 4];
    __shared__ __align__(16) float Bg[BK][BN];
    __shared__ __align__(16) float Bu[BK][BN];

    int tid = threadIdx.x;
    int tx = tid & 15, ty = tid >> 4;
    float accg[8][4] = {};
    float accu[8][4] = {};

    int  t_row  = 0;
    bool avalid = false;
    if (tid < 128) {
        int r = rbase + tid;
        if (r < segend) { t_row = g_tok[r]; avalid = true; }
    }

    for (int ck = 0; ck < H_ / BK; ck++) {
        int kk0 = ck * BK;
        if (tid < 128) {
            const float* xp = x + (size_t)t_row * H_ + kk0;
#pragma unroll
            for (int q = 0; q < 4; q++) {
                float4 v = make_float4(0.f, 0.f, 0.f, 0.f);
                if (avalid) v = *(const float4*)(xp + q * 4);
                As[q * 4 + 0][tid] = v.x; As[q * 4 + 1][tid] = v.y;
                As[q * 4 + 2][tid] = v.z; As[q * 4 + 3][tid] = v.w;
            }
        } else {
            int u = tid - 128;
#pragma unroll
            for (int i2 = 0; i2 < 4; i2++) {
                int slot = u + i2 * 128;
                int mat = slot >> 8;           // 0: gate, 1: up
                int q = slot & 255;
                int k = q >> 4, f = q & 15;
                const float* src = (mat ? wup : wgp) + (size_t)(kk0 + k) * I_ + nb + f * 4;
                float4 v = *(const float4*)src;
                if (mat) *(float4*)&Bu[k][f * 4] = v;
                else     *(float4*)&Bg[k][f * 4] = v;
            }
        }
        __syncthreads();
#pragma unroll
        for (int k = 0; k < BK; k++) {
            float4 a0 = *(const float4*)&As[k][ty * 8];
            float4 a1 = *(const float4*)&As[k][ty * 8 + 4];
            float a[8] = {a0.x, a0.y, a0.z, a0.w, a1.x, a1.y, a1.z, a1.w};
            float4 bg4 = *(const float4*)&Bg[k][tx * 4];
            float4 bu4 = *(const float4*)&Bu[k][tx * 4];
            float bgv[4] = {bg4.x, bg4.y, bg4.z, bg4.w};
            float buv[4] = {bu4.x, bu4.y, bu4.z, bu4.w};
#pragma unroll
            for (int i = 0; i < 8; i++) {
#pragma unroll
                for (int j = 0; j < 4; j++) {
                    accg[i][j] = fmaf(a[i], bgv[j], accg[i][j]);
                    accu[i][j] = fmaf(a[i], buv[j], accu[i][j]);
                }
            }
        }
        __syncthreads();
    }
#pragma unroll
    for (int i = 0; i < 8; i++) {
        int r = rbase + ty * 8 + i;
        float4 o = make_float4(0.f, 0.f, 0.f, 0.f);
        if (r < segend) {
            float v[4];
#pragma unroll
            for (int j = 0; j < 4; j++) {
                float g = accg[i][j];
                float s = g / (1.f + expf(-g));
                v[j] = s * accu[i][j];
            }
            o = make_float4(v[0], v[1], v[2], v[3]);
        }
        *(float4*)&g_hbuf[(size_t)r * I_ + nb + tx * 4] = o;
    }
}

// ---------------------- K3: routed down + weighted scatter -----------------
__global__ __launch_bounds__(256) void k3_down(const float* __restrict__ wd,
                                               float* __restrict__ out) {
    int e = g_tileexp[blockIdx.x];
    if (e < 0) return;
    int rbase  = blockIdx.x * BM;
    int nb     = blockIdx.y * BN;
    int segend = g_segend[e];
    const float* wdp = wd + (size_t)e * I_ * H_;

    __shared__ __align__(16) float As[BK][BM + 4];
    __shared__ __align__(16) float Bs[BK][BN];
    int tid = threadIdx.x;
    int tx = tid & 15, ty = tid >> 4;
    float acc[8][4] = {};

    for (int ck = 0; ck < I_ / BK; ck++) {
        int kk0 = ck * BK;
#pragma unroll
        for (int i2 = 0; i2 < 2; i2++) {
            int slot = tid + i2 * 256;
            int m = slot >> 2, f = slot & 3;
            float4 v = *(const float4*)&g_hbuf[(size_t)(rbase + m) * I_ + kk0 + f * 4];
            As[f * 4 + 0][m] = v.x; As[f * 4 + 1][m] = v.y;
            As[f * 4 + 2][m] = v.z; As[f * 4 + 3][m] = v.w;
        }
        {
            int k = tid >> 4, f = tid & 15;
            *(float4*)&Bs[k][f * 4] = *(const float4*)(wdp + (size_t)(kk0 + k) * H_ + nb + f * 4);
        }
        __syncthreads();
#pragma unroll
        for (int k = 0; k < BK; k++) {
            float4 a0 = *(const float4*)&As[k][ty * 8];
            float4 a1 = *(const float4*)&As[k][ty * 8 + 4];
            float a[8] = {a0.x, a0.y, a0.z, a0.w, a1.x, a1.y, a1.z, a1.w};
            float4 b4 = *(const float4*)&Bs[k][tx * 4];
            float bv[4] = {b4.x, b4.y, b4.z, b4.w};
#pragma unroll
            for (int i = 0; i < 8; i++)
#pragma unroll
                for (int j = 0; j < 4; j++)
                    acc[i][j] = fmaf(a[i], bv[j], acc[i][j]);
        }
        __syncthreads();
    }
#pragma unroll
    for (int i = 0; i < 8; i++) {
        int r = rbase + ty * 8 + i;
        if (r < segend) {
            int tt = g_tok[r];
            float w = g_wt[r];
            float* op = out + (size_t)tt * H_ + nb + tx * 4;
#pragma unroll
            for (int j = 0; j < 4; j++) atomicAdd(op + j, w * acc[i][j]);
        }
    }
}

// -------------- K4: shared conv-gate (3 shifted GEMMs) + up, fused ---------
// shbuf[t,:] = silu(sum_k x[t-2+k] @ convT[k]) * (x[t] @ sup)
__global__ __launch_bounds__(256) void k4_shared_gateup(const float* __restrict__ x,
                                                        const float* __restrict__ sup) {
    int mb = blockIdx.x * BM;
    int nb = blockIdx.y * BN;
    __shared__ __align__(16) float As[BK][BM + 4];
    __shared__ __align__(16) float Bs[BK][BN];
    int tid = threadIdx.x;
    int tx = tid & 15, ty = tid >> 4;
    float accg[8][4] = {};
    float accu[8][4] = {};

#pragma unroll 1
    for (int ck = 0; ck < 4 * (H_ / BK); ck++) {
        int grp = ck >> 6;                 // 0,1,2: conv taps (shift 2,1,0); 3: up
        int kk0 = (ck & 63) * BK;
        int d = (grp == 0) ? 2 : ((grp == 1) ? 1 : 0);
        const float* bsrc = (grp < 3)
            ? (g_convT + (size_t)grp * H_ * I_ + (size_t)kk0 * I_ + nb)
            : (sup + (size_t)kk0 * I_ + nb);
#pragma unroll
        for (int i2 = 0; i2 < 2; i2++) {
            int slot = tid + i2 * 256;
            int m = slot >> 2, f = slot & 3;
            int gm = mb + m;
            float4 v = make_float4(0.f, 0.f, 0.f, 0.f);
            if ((gm & (S_ - 1)) >= d)      // causal: zero across batch boundary
                v = *(const float4*)&x[(size_t)(gm - d) * H_ + kk0 + f * 4];
            As[f * 4 + 0][m] = v.x; As[f * 4 + 1][m] = v.y;
            As[f * 4 + 2][m] = v.z; As[f * 4 + 3][m] = v.w;
        }
        {
            int k = tid >> 4, f = tid & 15;
            *(float4*)&Bs[k][f * 4] = *(const float4*)(bsrc + (size_t)k * I_ + f * 4);
        }
        __syncthreads();
        if (grp < 3) {
#pragma unroll
            for (int k = 0; k < BK; k++) {
                float4 a0 = *(const float4*)&As[k][ty * 8];
                float4 a1 = *(const float4*)&As[k][ty * 8 + 4];
                float a[8] = {a0.x, a0.y, a0.z, a0.w, a1.x, a1.y, a1.z, a1.w};
                float4 b4 = *(const float4*)&Bs[k][tx * 4];
                float bv[4] = {b4.x, b4.y, b4.z, b4.w};
#pragma unroll
                for (int i = 0; i < 8; i++)
#pragma unroll
                    for (int j = 0; j < 4; j++)
                        accg[i][j] = fmaf(a[i], bv[j], accg[i][j]);
            }
        } else {
#pragma unroll
            for (int k = 0; k < BK; k++) {
                float4 a0 = *(const float4*)&As[k][ty * 8];
                float4 a1 = *(const float4*)&As[k][ty * 8 + 4];
                float a[8] = {a0.x, a0.y, a0.z, a0.w, a1.x, a1.y, a1.z, a1.w};
                float4 b4 = *(const float4*)&Bs[k][tx * 4];
                float bv[4] = {b4.x, b4.y, b4.z, b4.w};
#pragma unroll
                for (int i = 0; i < 8; i++)
#pragma unroll
                    for (int j = 0; j < 4; j++)
                        accu[i][j] = fmaf(a[i], bv[j], accu[i][j]);
            }
        }
        __syncthreads();
    }
#pragma unroll
    for (int i = 0; i < 8; i++) {
        int m = mb + ty * 8 + i;
        float v[4];
#pragma unroll
        for (int j = 0; j < 4; j++) {
            float g = accg[i][j];
            float s = g / (1.f + expf(-g));
            v[j] = s * accu[i][j];
        }
        *(float4*)&g_shbuf[(size_t)m * I_ + nb + tx * 4] = make_float4(v[0], v[1], v[2], v[3]);
    }
}

// ---------------------- K5: shared down, out += ----------------------------
__global__ __launch_bounds__(256) void k5_shared_down(const float* __restrict__ sdn,
                                                      float* __restrict__ out) {
    int mb = blockIdx.x * BM;
    int nb = blockIdx.y * BN;
    __shared__ __align__(16) float As[BK][BM + 4];
    __shared__ __align__(16) float Bs[BK][BN];
    int tid = threadIdx.x;
    int tx = tid & 15, ty = tid >> 4;
    float acc[8][4] = {};

    for (int ck = 0; ck < I_ / BK; ck++) {
        int kk0 = ck * BK;
#pragma unroll
        for (int i2 = 0; i2 < 2; i2++) {
            int slot = tid + i2 * 256;
            int m = slot >> 2, f = slot & 3;
            float4 v = *(const float4*)&g_shbuf[(size_t)(mb + m) * I_ + kk0 + f * 4];
            As[f * 4 + 0][m] = v.x; As[f * 4 + 1][m] = v.y;
            As[f * 4 + 2][m] = v.z; As[f * 4 + 3][m] = v.w;
        }
        {
            int k = tid >> 4, f = tid & 15;
            *(float4*)&Bs[k][f * 4] = *(const float4*)(sdn + (size_t)(kk0 + k) * H_ + nb + f * 4);
        }
        __syncthreads();
#pragma unroll
        for (int k = 0; k < BK; k++) {
            float4 a0 = *(const float4*)&As[k][ty * 8];
            float4 a1 = *(const float4*)&As[k][ty * 8 + 4];
            float a[8] = {a0.x, a0.y, a0.z, a0.w, a1.x, a1.y, a1.z, a1.w};
            float4 b4 = *(const float4*)&Bs[k][tx * 4];
            float bv[4] = {b4.x, b4.y, b4.z, b4.w};
#pragma unroll
            for (int i = 0; i < 8; i++)
#pragma unroll
                for (int j = 0; j < 4; j++)
                    acc[i][j] = fmaf(a[i], bv[j], acc[i][j]);
        }
        __syncthreads();
    }
#pragma unroll
    for (int i = 0; i < 8; i++) {
        int m = mb + ty * 8 + i;
        float* op = out + (size_t)m * H_ + nb + tx * 4;
        float4 o = *(const float4*)op;
        o.x += acc[i][0]; o.y += acc[i][1]; o.z += acc[i][2]; o.w += acc[i][3];
        *(float4*)op = o;
    }
}

// ------------------------------- launcher ----------------------------------
extern "C" void kernel_launch(void* const* d_in, const int* in_sizes, int n_in,
                              void* d_out, int out_size) {
    const float* x   = (const float*)d_in[0];  // hidden_states (B,S,H)
    const float* rw  = (const float*)d_in[1];  // router_w (H,E)
    const float* rb  = (const float*)d_in[2];  // router_bias (E)
    const float* wg  = (const float*)d_in[3];  // expert_gate_w (15,H,I)
    const float* wu  = (const float*)d_in[4];  // expert_up_w (15,H,I)
    const float* wd  = (const float*)d_in[5];  // expert_down_w (15,I,H)
    const float* cw  = (const float*)d_in[6];  // conv_w (I,H,KS)
    const float* sup = (const float*)d_in[7];  // shared_up_w (H,I)
    const float* sdn = (const float*)d_in[8];  // shared_down_w (I,H)
    float* out = (float*)d_out;

    k_prep_conv<<<(KS_ * H_ * I_ + 255) / 256, 256>>>(cw);
    k_router<<<T_ / 8, 256>>>(x, rw, rb, out);
    k_offsets<<<1, 1>>>();
    k_scatter<<<(T_ + 255) / 256, 256>>>();
    k2_gateup<<<dim3(NTILES, I_ / BN), 256>>>(x, wg, wu);
    k3_down<<<dim3(NTILES, H_ / BN), 256>>>(wd, out);
    k4_shared_gateup<<<dim3(T_ / BM, I_ / BN), 256>>>(x, sup);
    k5_shared_down<<<dim3(T_ / BM, H_ / BN), 256>>>(sdn, out);
}

// round 4
// speedup vs baseline: 1.4180x; 1.4180x over previous
#include <cuda_runtime.h>
#include <cuda_bf16.h>
#include <math.h>

// ---------------------------------------------------------------------------
// BiBoMoE layer, GB300 R2: bf16 3-pass tensor-core GEMMs (mma.m16n8k16)
//   B=4 S=4096 H=1024 I=512 E=16 TOPK=2 KS=3   T=16384 tokens
// ---------------------------------------------------------------------------

#define B_  4
#define S_  4096
#define H_  1024
#define I_  512
#define E_  16
#define KS_ 3
#define T_  (B_ * S_)          // 16384
#define NROUTED 15

#define BM 128
#define BN 64
#define BKT 32                 // k-tile (2 x k16 mma steps)
#define AP 40                  // smem k-pitch in bf16 elems (bank-conflict-free)
#define PMAX   34816           // 2T + padding slack, multiple of BM
#define NTILES (PMAX / BM)     // 272

typedef unsigned short u16;

// ------------------------- device scratch (static) -------------------------
__device__ __align__(16) float g_hbuf[PMAX * I_];       // routed silu(g)*u
__device__ __align__(16) float g_shbuf[T_ * I_];        // shared silu(gate)*up
__device__ __align__(16) float g_convT[KS_ * H_ * I_];  // conv_w -> [k][h][i]
__device__ int   g_tok[PMAX];
__device__ float g_wt[PMAX];
__device__ int   g_cnt[E_];
__device__ int   g_cur[E_];
__device__ int   g_segend[E_];
__device__ int   g_tileexp[NTILES];
__device__ int   g_top_e[T_ * 2];
__device__ float g_top_w[T_ * 2];

// ------------------------------ helpers ------------------------------------
__device__ __forceinline__ void split_store(float x, u16* ph, u16* pl) {
    __nv_bfloat16 h = __float2bfloat16(x);           // rn
    float hf = __bfloat162float(h);
    __nv_bfloat16 l = __float2bfloat16(x - hf);      // exact residual, rn to bf16
    *ph = __bfloat16_as_ushort(h);
    *pl = __bfloat16_as_ushort(l);
}

__device__ __forceinline__ void mma16816(float d[4], const unsigned* a, const unsigned* b) {
    asm volatile(
        "mma.sync.aligned.m16n8k16.row.col.f32.bf16.bf16.f32 "
        "{%0,%1,%2,%3}, {%4,%5,%6,%7}, {%8,%9}, {%0,%1,%2,%3};\n"
        : "+f"(d[0]), "+f"(d[1]), "+f"(d[2]), "+f"(d[3])
        : "r"(a[0]), "r"(a[1]), "r"(a[2]), "r"(a[3]), "r"(b[0]), "r"(b[1]));
}

__device__ __forceinline__ float silu_f(float g) { return g / (1.f + expf(-g)); }

// ------------------------------ tiny kernels -------------------------------
__global__ void k_prep_conv(const float* __restrict__ cw) {
    int idx = blockIdx.x * blockDim.x + threadIdx.x;
    if (idx < E_) g_cnt[idx] = 0;
    if (idx >= KS_ * H_ * I_) return;
    int i = idx % I_;
    int h = (idx / I_) % H_;
    int k = idx / (I_ * H_);
    g_convT[idx] = cw[(size_t)i * (H_ * KS_) + h * KS_ + k];
}

__global__ void k_router(const float* __restrict__ x, const float* __restrict__ rw,
                         const float* __restrict__ rb, float* __restrict__ out) {
    int gw   = (blockIdx.x * blockDim.x + threadIdx.x) >> 5;
    int lane = threadIdx.x & 31;
    if (gw >= T_) return;
    const float* xt = x + (size_t)gw * H_;

    float acc[E_];
#pragma unroll
    for (int e = 0; e < E_; e++) acc[e] = 0.f;

    for (int j = 0; j < H_ / 32; j++) {
        int h = j * 32 + lane;
        float xv = xt[h];
        const float* wr = rw + (size_t)h * E_;
        float4 w0 = *(const float4*)(wr);
        float4 w1 = *(const float4*)(wr + 4);
        float4 w2 = *(const float4*)(wr + 8);
        float4 w3 = *(const float4*)(wr + 12);
        acc[0]  = fmaf(xv, w0.x, acc[0]);  acc[1]  = fmaf(xv, w0.y, acc[1]);
        acc[2]  = fmaf(xv, w0.z, acc[2]);  acc[3]  = fmaf(xv, w0.w, acc[3]);
        acc[4]  = fmaf(xv, w1.x, acc[4]);  acc[5]  = fmaf(xv, w1.y, acc[5]);
        acc[6]  = fmaf(xv, w1.z, acc[6]);  acc[7]  = fmaf(xv, w1.w, acc[7]);
        acc[8]  = fmaf(xv, w2.x, acc[8]);  acc[9]  = fmaf(xv, w2.y, acc[9]);
        acc[10] = fmaf(xv, w2.z, acc[10]); acc[11] = fmaf(xv, w2.w, acc[11]);
        acc[12] = fmaf(xv, w3.x, acc[12]); acc[13] = fmaf(xv, w3.y, acc[13]);
        acc[14] = fmaf(xv, w3.z, acc[14]); acc[15] = fmaf(xv, w3.w, acc[15]);
    }
#pragma unroll
    for (int e = 0; e < E_; e++) {
#pragma unroll
        for (int off = 16; off > 0; off >>= 1)
            acc[e] += __shfl_xor_sync(0xffffffffu, acc[e], off);
    }
#pragma unroll
    for (int e = 0; e < E_; e++) acc[e] += rb[e];

    float mx = acc[0];
#pragma unroll
    for (int e = 1; e < E_; e++) mx = fmaxf(mx, acc[e]);
    float p[E_], S = 0.f;
#pragma unroll
    for (int e = 0; e < E_; e++) { p[e] = expf(acc[e] - mx); S += p[e]; }

    int i1 = 0;
#pragma unroll
    for (int e = 1; e < E_; e++) if (p[e] > p[i1]) i1 = e;
    int i2 = (i1 == 0) ? 1 : 0;
#pragma unroll
    for (int e = 0; e < E_; e++) if (e != i1 && p[e] > p[i2]) i2 = e;

    float invS = 1.f / S;
    float w1 = p[i1] * invS, w2 = p[i2] * invS;
    float inv = 1.f / (w1 + w2 + 1e-6f);
    float nw1 = w1 * inv, nw2 = w2 * inv;
    float wid = (i1 == E_ - 1) ? nw1 : ((i2 == E_ - 1) ? nw2 : 0.f);

    if (lane == 0) {
        g_top_e[2 * gw]     = i1; g_top_w[2 * gw]     = nw1;
        g_top_e[2 * gw + 1] = i2; g_top_w[2 * gw + 1] = nw2;
        if (i1 < NROUTED) atomicAdd(&g_cnt[i1], 1);
        if (i2 < NROUTED) atomicAdd(&g_cnt[i2], 1);
    }
    float* ot = out + (size_t)gw * H_;
    for (int j = 0; j < H_ / 32; j++) {
        int h = j * 32 + lane;
        ot[h] = wid * xt[h];
    }
}

__global__ void k_offsets() {
    if (threadIdx.x != 0 || blockIdx.x != 0) return;
    for (int tt = 0; tt < NTILES; tt++) g_tileexp[tt] = -1;
    int o = 0;
    for (int e = 0; e < NROUTED; e++) {
        g_cur[e]    = o;
        g_segend[e] = o + g_cnt[e];
        int nt = (g_cnt[e] + BM - 1) / BM;
        for (int tt = 0; tt < nt; tt++) {
            int ti = o / BM + tt;
            if (ti < NTILES) g_tileexp[ti] = e;
        }
        o += nt * BM;
    }
}

__global__ void k_scatter() {
    int t = blockIdx.x * blockDim.x + threadIdx.x;
    if (t >= T_) return;
    for (int pqi = 0; pqi < 2; pqi++) {
        int e = g_top_e[2 * t + pqi];
        if (e < NROUTED) {
            int pos = atomicAdd(&g_cur[e], 1);
            g_tok[pos] = t;
            g_wt[pos]  = g_top_w[2 * t + pqi];
        }
    }
}

// ---------------------- K2: routed gate+up (gather, dual-B) ----------------
__global__ __launch_bounds__(256) void k2_gateup(const float* __restrict__ x,
                                                 const float* __restrict__ wg,
                                                 const float* __restrict__ wu) {
    int e = g_tileexp[blockIdx.x];
    if (e < 0) return;
    int rbase  = blockIdx.x * BM;
    int nb     = blockIdx.y * BN;
    int segend = g_segend[e];
    const float* wgp = wg + (size_t)e * H_ * I_;
    const float* wup = wu + (size_t)e * H_ * I_;

    __shared__ __align__(16) u16 As_h[BM][AP], As_l[BM][AP];
    __shared__ __align__(16) u16 Bg_h[BN][AP], Bg_l[BN][AP];
    __shared__ __align__(16) u16 Bu_h[BN][AP], Bu_l[BN][AP];

    int tid = threadIdx.x;
    int wid = tid >> 5, lane = tid & 31;
    int gid = lane >> 2, tig = lane & 3;
    int wm = (wid & 3) * 32, wn = (wid >> 2) * 32;

    float dg[2][4][4] = {};
    float du[2][4][4] = {};

    int arow = tid >> 3;             // + i*32
    int af   = (tid & 7) * 4;
    int trow[4];
#pragma unroll
    for (int i = 0; i < 4; i++) {
        int r = rbase + arow + i * 32;
        trow[i] = (r < segend) ? g_tok[r] : -1;
    }

    for (int ck = 0; ck < H_ / BKT; ck++) {
        int kk0 = ck * BKT;
        // A tile (gathered), split to hi/lo bf16
#pragma unroll
        for (int i = 0; i < 4; i++) {
            int ml = arow + i * 32;
            float4 v = make_float4(0.f, 0.f, 0.f, 0.f);
            if (trow[i] >= 0)
                v = *(const float4*)&x[(size_t)trow[i] * H_ + kk0 + af];
            split_store(v.x, &As_h[ml][af + 0], &As_l[ml][af + 0]);
            split_store(v.y, &As_h[ml][af + 1], &As_l[ml][af + 1]);
            split_store(v.z, &As_h[ml][af + 2], &As_l[ml][af + 2]);
            split_store(v.w, &As_h[ml][af + 3], &As_l[ml][af + 3]);
        }
        // B tiles (gate + up), transposed to [n][k], split
#pragma unroll
        for (int i = 0; i < 4; i++) {
            int slot = tid + i * 256;
            int mat = slot >> 9;
            int q = slot & 511;
            int k = q >> 4, nq = (q & 15) * 4;
            const float* src = (mat ? wup : wgp) + (size_t)(kk0 + k) * I_ + nb + nq;
            float4 v = *(const float4*)src;
            if (mat) {
                split_store(v.x, &Bu_h[nq + 0][k], &Bu_l[nq + 0][k]);
                split_store(v.y, &Bu_h[nq + 1][k], &Bu_l[nq + 1][k]);
                split_store(v.z, &Bu_h[nq + 2][k], &Bu_l[nq + 2][k]);
                split_store(v.w, &Bu_h[nq + 3][k], &Bu_l[nq + 3][k]);
            } else {
                split_store(v.x, &Bg_h[nq + 0][k], &Bg_l[nq + 0][k]);
                split_store(v.y, &Bg_h[nq + 1][k], &Bg_l[nq + 1][k]);
                split_store(v.z, &Bg_h[nq + 2][k], &Bg_l[nq + 2][k]);
                split_store(v.w, &Bg_h[nq + 3][k], &Bg_l[nq + 3][k]);
            }
        }
        __syncthreads();
#pragma unroll
        for (int ks = 0; ks < 2; ks++) {
            int kc = ks * 16;
            unsigned ah[2][4], al[2][4];
#pragma unroll
            for (int mf = 0; mf < 2; mf++) {
                int m0 = wm + mf * 16;
                ah[mf][0] = *(const unsigned*)&As_h[m0 + gid][kc + 2 * tig];
                ah[mf][1] = *(const unsigned*)&As_h[m0 + gid + 8][kc + 2 * tig];
                ah[mf][2] = *(const unsigned*)&As_h[m0 + gid][kc + 2 * tig + 8];
                ah[mf][3] = *(const unsigned*)&As_h[m0 + gid + 8][kc + 2 * tig + 8];
                al[mf][0] = *(const unsigned*)&As_l[m0 + gid][kc + 2 * tig];
                al[mf][1] = *(const unsigned*)&As_l[m0 + gid + 8][kc + 2 * tig];
                al[mf][2] = *(const unsigned*)&As_l[m0 + gid][kc + 2 * tig + 8];
                al[mf][3] = *(const unsigned*)&As_l[m0 + gid + 8][kc + 2 * tig + 8];
            }
#pragma unroll
            for (int nf = 0; nf < 4; nf++) {
                int n0 = wn + nf * 8 + gid;
                unsigned bgh[2], bgl[2], buh[2], bul[2];
                bgh[0] = *(const unsigned*)&Bg_h[n0][kc + 2 * tig];
                bgh[1] = *(const unsigned*)&Bg_h[n0][kc + 2 * tig + 8];
                bgl[0] = *(const unsigned*)&Bg_l[n0][kc + 2 * tig];
                bgl[1] = *(const unsigned*)&Bg_l[n0][kc + 2 * tig + 8];
                buh[0] = *(const unsigned*)&Bu_h[n0][kc + 2 * tig];
                buh[1] = *(const unsigned*)&Bu_h[n0][kc + 2 * tig + 8];
                bul[0] = *(const unsigned*)&Bu_l[n0][kc + 2 * tig];
                bul[1] = *(const unsigned*)&Bu_l[n0][kc + 2 * tig + 8];
#pragma unroll
                for (int mf = 0; mf < 2; mf++) {
                    mma16816(dg[mf][nf], ah[mf], bgh);
                    mma16816(dg[mf][nf], al[mf], bgh);
                    mma16816(dg[mf][nf], ah[mf], bgl);
                    mma16816(du[mf][nf], ah[mf], buh);
                    mma16816(du[mf][nf], al[mf], buh);
                    mma16816(du[mf][nf], ah[mf], bul);
                }
            }
        }
        __syncthreads();
    }
    // epilogue: silu(g)*u, zeros on padded rows
#pragma unroll
    for (int mf = 0; mf < 2; mf++)
#pragma unroll
        for (int nf = 0; nf < 4; nf++) {
            int n0 = nb + wn + nf * 8 + 2 * tig;
#pragma unroll
            for (int half = 0; half < 2; half++) {
                int r = rbase + wm + mf * 16 + gid + half * 8;
                float2 o = make_float2(0.f, 0.f);
                if (r < segend) {
                    float g0 = dg[mf][nf][half * 2 + 0], u0 = du[mf][nf][half * 2 + 0];
                    float g1 = dg[mf][nf][half * 2 + 1], u1 = du[mf][nf][half * 2 + 1];
                    o.x = silu_f(g0) * u0;
                    o.y = silu_f(g1) * u1;
                }
                *(float2*)&g_hbuf[(size_t)r * I_ + n0] = o;
            }
        }
}

// ---------------------- K3: routed down + weighted scatter -----------------
__global__ __launch_bounds__(256) void k3_down(const float* __restrict__ wd,
                                               float* __restrict__ out) {
    int e = g_tileexp[blockIdx.x];
    if (e < 0) return;
    int rbase  = blockIdx.x * BM;
    int nb     = blockIdx.y * BN;
    int segend = g_segend[e];
    const float* wdp = wd + (size_t)e * I_ * H_;

    __shared__ __align__(16) u16 As_h[BM][AP], As_l[BM][AP];
    __shared__ __align__(16) u16 Bs_h[BN][AP], Bs_l[BN][AP];

    int tid = threadIdx.x;
    int wid = tid >> 5, lane = tid & 31;
    int gid = lane >> 2, tig = lane & 3;
    int wm = (wid & 3) * 32, wn = (wid >> 2) * 32;

    float dd[2][4][4] = {};
    int arow = tid >> 3;
    int af   = (tid & 7) * 4;

    for (int ck = 0; ck < I_ / BKT; ck++) {
        int kk0 = ck * BKT;
#pragma unroll
        for (int i = 0; i < 4; i++) {
            int ml = arow + i * 32;
            float4 v = *(const float4*)&g_hbuf[(size_t)(rbase + ml) * I_ + kk0 + af];
            split_store(v.x, &As_h[ml][af + 0], &As_l[ml][af + 0]);
            split_store(v.y, &As_h[ml][af + 1], &As_l[ml][af + 1]);
            split_store(v.z, &As_h[ml][af + 2], &As_l[ml][af + 2]);
            split_store(v.w, &As_h[ml][af + 3], &As_l[ml][af + 3]);
        }
#pragma unroll
        for (int i = 0; i < 2; i++) {
            int slot = tid + i * 256;
            int k = slot >> 4, nq = (slot & 15) * 4;
            float4 v = *(const float4*)(wdp + (size_t)(kk0 + k) * H_ + nb + nq);
            split_store(v.x, &Bs_h[nq + 0][k], &Bs_l[nq + 0][k]);
            split_store(v.y, &Bs_h[nq + 1][k], &Bs_l[nq + 1][k]);
            split_store(v.z, &Bs_h[nq + 2][k], &Bs_l[nq + 2][k]);
            split_store(v.w, &Bs_h[nq + 3][k], &Bs_l[nq + 3][k]);
        }
        __syncthreads();
#pragma unroll
        for (int ks = 0; ks < 2; ks++) {
            int kc = ks * 16;
            unsigned ah[2][4], al[2][4];
#pragma unroll
            for (int mf = 0; mf < 2; mf++) {
                int m0 = wm + mf * 16;
                ah[mf][0] = *(const unsigned*)&As_h[m0 + gid][kc + 2 * tig];
                ah[mf][1] = *(const unsigned*)&As_h[m0 + gid + 8][kc + 2 * tig];
                ah[mf][2] = *(const unsigned*)&As_h[m0 + gid][kc + 2 * tig + 8];
                ah[mf][3] = *(const unsigned*)&As_h[m0 + gid + 8][kc + 2 * tig + 8];
                al[mf][0] = *(const unsigned*)&As_l[m0 + gid][kc + 2 * tig];
                al[mf][1] = *(const unsigned*)&As_l[m0 + gid + 8][kc + 2 * tig];
                al[mf][2] = *(const unsigned*)&As_l[m0 + gid][kc + 2 * tig + 8];
                al[mf][3] = *(const unsigned*)&As_l[m0 + gid + 8][kc + 2 * tig + 8];
            }
#pragma unroll
            for (int nf = 0; nf < 4; nf++) {
                int n0 = wn + nf * 8 + gid;
                unsigned bh[2], bl[2];
                bh[0] = *(const unsigned*)&Bs_h[n0][kc + 2 * tig];
                bh[1] = *(const unsigned*)&Bs_h[n0][kc + 2 * tig + 8];
                bl[0] = *(const unsigned*)&Bs_l[n0][kc + 2 * tig];
                bl[1] = *(const unsigned*)&Bs_l[n0][kc + 2 * tig + 8];
#pragma unroll
                for (int mf = 0; mf < 2; mf++) {
                    mma16816(dd[mf][nf], ah[mf], bh);
                    mma16816(dd[mf][nf], al[mf], bh);
                    mma16816(dd[mf][nf], ah[mf], bl);
                }
            }
        }
        __syncthreads();
    }
#pragma unroll
    for (int mf = 0; mf < 2; mf++)
#pragma unroll
        for (int half = 0; half < 2; half++) {
            int r = rbase + wm + mf * 16 + gid + half * 8;
            if (r < segend) {
                int tt = g_tok[r];
                float w = g_wt[r];
                float* op = out + (size_t)tt * H_;
#pragma unroll
                for (int nf = 0; nf < 4; nf++) {
                    int n0 = nb + wn + nf * 8 + 2 * tig;
                    atomicAdd(op + n0,     w * dd[mf][nf][half * 2 + 0]);
                    atomicAdd(op + n0 + 1, w * dd[mf][nf][half * 2 + 1]);
                }
            }
        }
}

// -------------- K4: shared conv-gate (3 shifted GEMMs) + up, fused ---------
__global__ __launch_bounds__(256) void k4_shared_gateup(const float* __restrict__ x,
                                                        const float* __restrict__ sup) {
    int mb = blockIdx.x * BM;
    int nb = blockIdx.y * BN;

    __shared__ __align__(16) u16 As_h[BM][AP], As_l[BM][AP];
    __shared__ __align__(16) u16 Bs_h[BN][AP], Bs_l[BN][AP];

    int tid = threadIdx.x;
    int wid = tid >> 5, lane = tid & 31;
    int gid = lane >> 2, tig = lane & 3;
    int wm = (wid & 3) * 32, wn = (wid >> 2) * 32;

    float dg[2][4][4] = {};
    float du[2][4][4] = {};
    int arow = tid >> 3;
    int af   = (tid & 7) * 4;

#pragma unroll 1
    for (int ck = 0; ck < 4 * (H_ / BKT); ck++) {
        int grp = ck >> 5;                 // 0,1,2: conv taps (shift 2,1,0); 3: up
        int kk0 = (ck & 31) * BKT;
        int d = (grp == 0) ? 2 : ((grp == 1) ? 1 : 0);
        const float* bsrc = (grp < 3)
            ? (g_convT + (size_t)grp * H_ * I_ + (size_t)kk0 * I_ + nb)
            : (sup + (size_t)kk0 * I_ + nb);
#pragma unroll
        for (int i = 0; i < 4; i++) {
            int ml = arow + i * 32;
            int gm = mb + ml;
            float4 v = make_float4(0.f, 0.f, 0.f, 0.f);
            if ((gm & (S_ - 1)) >= d)
                v = *(const float4*)&x[(size_t)(gm - d) * H_ + kk0 + af];
            split_store(v.x, &As_h[ml][af + 0], &As_l[ml][af + 0]);
            split_store(v.y, &As_h[ml][af + 1], &As_l[ml][af + 1]);
            split_store(v.z, &As_h[ml][af + 2], &As_l[ml][af + 2]);
            split_store(v.w, &As_h[ml][af + 3], &As_l[ml][af + 3]);
        }
#pragma unroll
        for (int i = 0; i < 2; i++) {
            int slot = tid + i * 256;
            int k = slot >> 4, nq = (slot & 15) * 4;
            float4 v = *(const float4*)(bsrc + (size_t)k * I_ + nq);
            split_store(v.x, &Bs_h[nq + 0][k], &Bs_l[nq + 0][k]);
            split_store(v.y, &Bs_h[nq + 1][k], &Bs_l[nq + 1][k]);
            split_store(v.z, &Bs_h[nq + 2][k], &Bs_l[nq + 2][k]);
            split_store(v.w, &Bs_h[nq + 3][k], &Bs_l[nq + 3][k]);
        }
        __syncthreads();
#pragma unroll
        for (int ks = 0; ks < 2; ks++) {
            int kc = ks * 16;
            unsigned ah[2][4], al[2][4];
#pragma unroll
            for (int mf = 0; mf < 2; mf++) {
                int m0 = wm + mf * 16;
                ah[mf][0] = *(const unsigned*)&As_h[m0 + gid][kc + 2 * tig];
                ah[mf][1] = *(const unsigned*)&As_h[m0 + gid + 8][kc + 2 * tig];
                ah[mf][2] = *(const unsigned*)&As_h[m0 + gid][kc + 2 * tig + 8];
                ah[mf][3] = *(const unsigned*)&As_h[m0 + gid + 8][kc + 2 * tig + 8];
                al[mf][0] = *(const unsigned*)&As_l[m0 + gid][kc + 2 * tig];
                al[mf][1] = *(const unsigned*)&As_l[m0 + gid + 8][kc + 2 * tig];
                al[mf][2] = *(const unsigned*)&As_l[m0 + gid][kc + 2 * tig + 8];
                al[mf][3] = *(const unsigned*)&As_l[m0 + gid + 8][kc + 2 * tig + 8];
            }
#pragma unroll
            for (int nf = 0; nf < 4; nf++) {
                int n0 = wn + nf * 8 + gid;
                unsigned bh[2], bl[2];
                bh[0] = *(const unsigned*)&Bs_h[n0][kc + 2 * tig];
                bh[1] = *(const unsigned*)&Bs_h[n0][kc + 2 * tig + 8];
                bl[0] = *(const unsigned*)&Bs_l[n0][kc + 2 * tig];
                bl[1] = *(const unsigned*)&Bs_l[n0][kc + 2 * tig + 8];
                if (grp < 3) {
#pragma unroll
                    for (int mf = 0; mf < 2; mf++) {
                        mma16816(dg[mf][nf], ah[mf], bh);
                        mma16816(dg[mf][nf], al[mf], bh);
                        mma16816(dg[mf][nf], ah[mf], bl);
                    }
                } else {
#pragma unroll
                    for (int mf = 0; mf < 2; mf++) {
                        mma16816(du[mf][nf], ah[mf], bh);
                        mma16816(du[mf][nf], al[mf], bh);
                        mma16816(du[mf][nf], ah[mf], bl);
                    }
                }
            }
        }
        __syncthreads();
    }
#pragma unroll
    for (int mf = 0; mf < 2; mf++)
#pragma unroll
        for (int nf = 0; nf < 4; nf++) {
            int n0 = nb + wn + nf * 8 + 2 * tig;
#pragma unroll
            for (int half = 0; half < 2; half++) {
                int m = mb + wm + mf * 16 + gid + half * 8;
                float g0 = dg[mf][nf][half * 2 + 0], u0 = du[mf][nf][half * 2 + 0];
                float g1 = dg[mf][nf][half * 2 + 1], u1 = du[mf][nf][half * 2 + 1];
                float2 o;
                o.x = silu_f(g0) * u0;
                o.y = silu_f(g1) * u1;
                *(float2*)&g_shbuf[(size_t)m * I_ + n0] = o;
            }
        }
}

// ---------------------- K5: shared down, out += ----------------------------
__global__ __launch_bounds__(256) void k5_shared_down(const float* __restrict__ sdn,
                                                      float* __restrict__ out) {
    int mb = blockIdx.x * BM;
    int nb = blockIdx.y * BN;

    __shared__ __align__(16) u16 As_h[BM][AP], As_l[BM][AP];
    __shared__ __align__(16) u16 Bs_h[BN][AP], Bs_l[BN][AP];

    int tid = threadIdx.x;
    int wid = tid >> 5, lane = tid & 31;
    int gid = lane >> 2, tig = lane & 3;
    int wm = (wid & 3) * 32, wn = (wid >> 2) * 32;

    float dd[2][4][4] = {};
    int arow = tid >> 3;
    int af   = (tid & 7) * 4;

    for (int ck = 0; ck < I_ / BKT; ck++) {
        int kk0 = ck * BKT;
#pragma unroll
        for (int i = 0; i < 4; i++) {
            int ml = arow + i * 32;
            float4 v = *(const float4*)&g_shbuf[(size_t)(mb + ml) * I_ + kk0 + af];
            split_store(v.x, &As_h[ml][af + 0], &As_l[ml][af + 0]);
            split_store(v.y, &As_h[ml][af + 1], &As_l[ml][af + 1]);
            split_store(v.z, &As_h[ml][af + 2], &As_l[ml][af + 2]);
            split_store(v.w, &As_h[ml][af + 3], &As_l[ml][af + 3]);
        }
#pragma unroll
        for (int i = 0; i < 2; i++) {
            int slot = tid + i * 256;
            int k = slot >> 4, nq = (slot & 15) * 4;
            float4 v = *(const float4*)(sdn + (size_t)(kk0 + k) * H_ + nb + nq);
            split_store(v.x, &Bs_h[nq + 0][k], &Bs_l[nq + 0][k]);
            split_store(v.y, &Bs_h[nq + 1][k], &Bs_l[nq + 1][k]);
            split_store(v.z, &Bs_h[nq + 2][k], &Bs_l[nq + 2][k]);
            split_store(v.w, &Bs_h[nq + 3][k], &Bs_l[nq + 3][k]);
        }
        __syncthreads();
#pragma unroll
        for (int ks = 0; ks < 2; ks++) {
            int kc = ks * 16;
            unsigned ah[2][4], al[2][4];
#pragma unroll
            for (int mf = 0; mf < 2; mf++) {
                int m0 = wm + mf * 16;
                ah[mf][0] = *(const unsigned*)&As_h[m0 + gid][kc + 2 * tig];
                ah[mf][1] = *(const unsigned*)&As_h[m0 + gid + 8][kc + 2 * tig];
                ah[mf][2] = *(const unsigned*)&As_h[m0 + gid][kc + 2 * tig + 8];
                ah[mf][3] = *(const unsigned*)&As_h[m0 + gid + 8][kc + 2 * tig + 8];
                al[mf][0] = *(const unsigned*)&As_l[m0 + gid][kc + 2 * tig];
                al[mf][1] = *(const unsigned*)&As_l[m0 + gid + 8][kc + 2 * tig];
                al[mf][2] = *(const unsigned*)&As_l[m0 + gid][kc + 2 * tig + 8];
                al[mf][3] = *(const unsigned*)&As_l[m0 + gid + 8][kc + 2 * tig + 8];
            }
#pragma unroll
            for (int nf = 0; nf < 4; nf++) {
                int n0 = wn + nf * 8 + gid;
                unsigned bh[2], bl[2];
                bh[0] = *(const unsigned*)&Bs_h[n0][kc + 2 * tig];
                bh[1] = *(const unsigned*)&Bs_h[n0][kc + 2 * tig + 8];
                bl[0] = *(const unsigned*)&Bs_l[n0][kc + 2 * tig];
                bl[1] = *(const unsigned*)&Bs_l[n0][kc + 2 * tig + 8];
#pragma unroll
                for (int mf = 0; mf < 2; mf++) {
                    mma16816(dd[mf][nf], ah[mf], bh);
                    mma16816(dd[mf][nf], al[mf], bh);
                    mma16816(dd[mf][nf], ah[mf], bl);
                }
            }
        }
        __syncthreads();
    }
#pragma unroll
    for (int mf = 0; mf < 2; mf++)
#pragma unroll
        for (int nf = 0; nf < 4; nf++) {
            int n0 = nb + wn + nf * 8 + 2 * tig;
#pragma unroll
            for (int half = 0; half < 2; half++) {
                int m = mb + wm + mf * 16 + gid + half * 8;
                float* op = out + (size_t)m * H_ + n0;
                float2 o = *(const float2*)op;
                o.x += dd[mf][nf][half * 2 + 0];
                o.y += dd[mf][nf][half * 2 + 1];
                *(float2*)op = o;
            }
        }
}

// ------------------------------- launcher ----------------------------------
extern "C" void kernel_launch(void* const* d_in, const int* in_sizes, int n_in,
                              void* d_out, int out_size) {
    const float* x   = (const float*)d_in[0];
    const float* rw  = (const float*)d_in[1];
    const float* rb  = (const float*)d_in[2];
    const float* wg  = (const float*)d_in[3];
    const float* wu  = (const float*)d_in[4];
    const float* wd  = (const float*)d_in[5];
    const float* cw  = (const float*)d_in[6];
    const float* sup = (const float*)d_in[7];
    const float* sdn = (const float*)d_in[8];
    float* out = (float*)d_out;

    k_prep_conv<<<(KS_ * H_ * I_ + 255) / 256, 256>>>(cw);
    k_router<<<T_ / 8, 256>>>(x, rw, rb, out);
    k_offsets<<<1, 1>>>();
    k_scatter<<<(T_ + 255) / 256, 256>>>();
    k2_gateup<<<dim3(NTILES, I_ / BN), 256>>>(x, wg, wu);
    k3_down<<<dim3(NTILES, H_ / BN), 256>>>(wd, out);
    k4_shared_gateup<<<dim3(T_ / BM, I_ / BN), 256>>>(x, sup);
    k5_shared_down<<<dim3(T_ / BM, H_ / BN), 256>>>(sdn, out);
}

// round 14
// speedup vs baseline: 1.8683x; 1.3175x over previous
#include <cuda_runtime.h>
#include <cuda_bf16.h>
#include <math.h>

// ---------------------------------------------------------------------------
// BiBoMoE layer, GB300 R6: bf16 3-pass tensor-core GEMMs, pre-split operands
//   (R4 + fix: __device__ symbols resolved in device code, not passed as args)
//   B=4 S=4096 H=1024 I=512 E=16 TOPK=2 KS=3   T=16384 tokens
// ---------------------------------------------------------------------------

#define B_  4
#define S_  4096
#define H_  1024
#define I_  512
#define E_  16
#define KS_ 3
#define T_  (B_ * S_)          // 16384
#define NROUTED 15

#define BM 128
#define BN 64
#define BKT 32                 // k-tile (2 x k16 mma steps)
#define AP 40                  // smem k-pitch in u16 (80B rows, 16B aligned)
#define PMAX   34816           // 2T + padding slack, multiple of BM
#define NTILES (PMAX / BM)     // 272

typedef unsigned short u16;

// ------------------------- device scratch (static) -------------------------
// pre-split bf16 hi/lo operands (one-time prep)
__device__ __align__(16) u16 g_xh[T_ * H_],  g_xl[T_ * H_];                 // x [t][h]
__device__ __align__(16) u16 g_wgTh[NROUTED * I_ * H_], g_wgTl[NROUTED * I_ * H_]; // [e][n=i][k=h]
__device__ __align__(16) u16 g_wuTh[NROUTED * I_ * H_], g_wuTl[NROUTED * I_ * H_];
__device__ __align__(16) u16 g_wdTh[NROUTED * H_ * I_], g_wdTl[NROUTED * H_ * I_]; // [e][n=h][k=i]
__device__ __align__(16) u16 g_cth[KS_ * I_ * H_], g_ctl[KS_ * I_ * H_];    // [tap][n=i][k=h]
__device__ __align__(16) u16 g_supTh[I_ * H_], g_supTl[I_ * H_];            // [n=i][k=h]
__device__ __align__(16) u16 g_sdnTh[H_ * I_], g_sdnTl[H_ * I_];            // [n=h][k=i]
// pre-split intermediates
__device__ __align__(16) u16 g_hbh[(size_t)PMAX * I_], g_hbl[(size_t)PMAX * I_];
__device__ __align__(16) u16 g_shh[(size_t)T_ * I_],   g_shl[(size_t)T_ * I_];
// routing state
__device__ int   g_tok[PMAX];
__device__ float g_wt[PMAX];
__device__ int   g_cnt[E_];
__device__ int   g_cur[E_];
__device__ int   g_segend[E_];
__device__ int   g_tileexp[NTILES];
__device__ int   g_top_e[T_ * 2];
__device__ float g_top_w[T_ * 2];

// ------------------------------ helpers ------------------------------------
__device__ __forceinline__ void split2(float x, u16& h, u16& l) {
    __nv_bfloat16 hb = __float2bfloat16(x);
    float hf = __bfloat162float(hb);
    __nv_bfloat16 lb = __float2bfloat16(x - hf);
    h = __bfloat16_as_ushort(hb);
    l = __bfloat16_as_ushort(lb);
}

__device__ __forceinline__ void mma16816(float d[4], const unsigned* a, const unsigned* b) {
    asm volatile(
        "mma.sync.aligned.m16n8k16.row.col.f32.bf16.bf16.f32 "
        "{%0,%1,%2,%3}, {%4,%5,%6,%7}, {%8,%9}, {%0,%1,%2,%3};\n"
        : "+f"(d[0]), "+f"(d[1]), "+f"(d[2]), "+f"(d[3])
        : "r"(a[0]), "r"(a[1]), "r"(a[2]), "r"(a[3]), "r"(b[0]), "r"(b[1]));
}

__device__ __forceinline__ float silu_f(float g) { return g / (1.f + expf(-g)); }

// ------------------------------ prep kernels -------------------------------
// x -> xh/xl, 4 elems/thread, packed 8B stores
__global__ void k_split_x(const float* __restrict__ x) {
    size_t i = (size_t)(blockIdx.x * blockDim.x + threadIdx.x) * 4;
    float4 v = *(const float4*)&x[i];
    u16 h0, l0, h1, l1, h2, l2, h3, l3;
    split2(v.x, h0, l0); split2(v.y, h1, l1);
    split2(v.z, h2, l2); split2(v.w, h3, l3);
    *(uint2*)&g_xh[i] = make_uint2((unsigned)h0 | ((unsigned)h1 << 16),
                                   (unsigned)h2 | ((unsigned)h3 << 16));
    *(uint2*)&g_xl[i] = make_uint2((unsigned)l0 | ((unsigned)l1 << 16),
                                   (unsigned)l2 | ((unsigned)l3 << 16));
}

// generic tiled transpose + split: in [R][C] fp32 -> out hi/lo [C][R] u16.
// Output buffers selected DEVICE-SIDE via `which` (0=wg 1=wu 2=wd 3=sup 4=sdn)
// -- __device__ symbols must not be passed as kernel args from host code.
// grid (C/32, R/32, batch), block (32, 8)
__global__ void k_tsplit(const float* __restrict__ in, int which, int R, int C) {
    u16* oh; u16* ol;
    switch (which) {
        case 0:  oh = g_wgTh;  ol = g_wgTl;  break;
        case 1:  oh = g_wuTh;  ol = g_wuTl;  break;
        case 2:  oh = g_wdTh;  ol = g_wdTl;  break;
        case 3:  oh = g_supTh; ol = g_supTl; break;
        default: oh = g_sdnTh; ol = g_sdnTl; break;
    }
    __shared__ float t[32][33];
    size_t bo = (size_t)blockIdx.z * R * C;
    const float* ip = in + bo;
    u16* ohp = oh + bo;
    u16* olp = ol + bo;
    int c0 = blockIdx.x * 32, r0 = blockIdx.y * 32;
    int tx = threadIdx.x;
    for (int i = threadIdx.y; i < 32; i += 8)
        t[i][tx] = ip[(size_t)(r0 + i) * C + c0 + tx];
    __syncthreads();
    for (int i = threadIdx.y; i < 32; i += 8) {
        float v = t[tx][i];           // in[r0+tx][c0+i] -> out[c0+i][r0+tx]
        u16 h, l; split2(v, h, l);
        size_t o = (size_t)(c0 + i) * R + r0 + tx;
        ohp[o] = h; olp[o] = l;
    }
}

// conv_w (I,H,KS) -> cth/ctl [tap][i][h]; also zero counters
__global__ void k_prep_conv(const float* __restrict__ cw) {
    int idx = blockIdx.x * blockDim.x + threadIdx.x;
    if (idx < E_) g_cnt[idx] = 0;
    if (idx >= KS_ * I_ * H_) return;
    int h = idx % H_;
    int i = (idx / H_) % I_;
    int tap = idx / (I_ * H_);
    u16 hh, ll;
    split2(cw[(size_t)i * (H_ * KS_) + h * KS_ + tap], hh, ll);
    g_cth[idx] = hh; g_ctl[idx] = ll;
}

// ------------------------------ routing kernels ----------------------------
__global__ void k_router(const float* __restrict__ x, const float* __restrict__ rw,
                         const float* __restrict__ rb, float* __restrict__ out) {
    int gw   = (blockIdx.x * blockDim.x + threadIdx.x) >> 5;
    int lane = threadIdx.x & 31;
    if (gw >= T_) return;
    const float* xt = x + (size_t)gw * H_;

    float acc[E_];
#pragma unroll
    for (int e = 0; e < E_; e++) acc[e] = 0.f;

    for (int j = 0; j < H_ / 32; j++) {
        int h = j * 32 + lane;
        float xv = xt[h];
        const float* wr = rw + (size_t)h * E_;
        float4 w0 = *(const float4*)(wr);
        float4 w1 = *(const float4*)(wr + 4);
        float4 w2 = *(const float4*)(wr + 8);
        float4 w3 = *(const float4*)(wr + 12);
        acc[0]  = fmaf(xv, w0.x, acc[0]);  acc[1]  = fmaf(xv, w0.y, acc[1]);
        acc[2]  = fmaf(xv, w0.z, acc[2]);  acc[3]  = fmaf(xv, w0.w, acc[3]);
        acc[4]  = fmaf(xv, w1.x, acc[4]);  acc[5]  = fmaf(xv, w1.y, acc[5]);
        acc[6]  = fmaf(xv, w1.z, acc[6]);  acc[7]  = fmaf(xv, w1.w, acc[7]);
        acc[8]  = fmaf(xv, w2.x, acc[8]);  acc[9]  = fmaf(xv, w2.y, acc[9]);
        acc[10] = fmaf(xv, w2.z, acc[10]); acc[11] = fmaf(xv, w2.w, acc[11]);
        acc[12] = fmaf(xv, w3.x, acc[12]); acc[13] = fmaf(xv, w3.y, acc[13]);
        acc[14] = fmaf(xv, w3.z, acc[14]); acc[15] = fmaf(xv, w3.w, acc[15]);
    }
#pragma unroll
    for (int e = 0; e < E_; e++) {
#pragma unroll
        for (int off = 16; off > 0; off >>= 1)
            acc[e] += __shfl_xor_sync(0xffffffffu, acc[e], off);
    }
#pragma unroll
    for (int e = 0; e < E_; e++) acc[e] += rb[e];

    float mx = acc[0];
#pragma unroll
    for (int e = 1; e < E_; e++) mx = fmaxf(mx, acc[e]);
    float p[E_], S = 0.f;
#pragma unroll
    for (int e = 0; e < E_; e++) { p[e] = expf(acc[e] - mx); S += p[e]; }

    int i1 = 0;
#pragma unroll
    for (int e = 1; e < E_; e++) if (p[e] > p[i1]) i1 = e;
    int i2 = (i1 == 0) ? 1 : 0;
#pragma unroll
    for (int e = 0; e < E_; e++) if (e != i1 && p[e] > p[i2]) i2 = e;

    float invS = 1.f / S;
    float w1 = p[i1] * invS, w2 = p[i2] * invS;
    float inv = 1.f / (w1 + w2 + 1e-6f);
    float nw1 = w1 * inv, nw2 = w2 * inv;
    float wid = (i1 == E_ - 1) ? nw1 : ((i2 == E_ - 1) ? nw2 : 0.f);

    if (lane == 0) {
        g_top_e[2 * gw]     = i1; g_top_w[2 * gw]     = nw1;
        g_top_e[2 * gw + 1] = i2; g_top_w[2 * gw + 1] = nw2;
        if (i1 < NROUTED) atomicAdd(&g_cnt[i1], 1);
        if (i2 < NROUTED) atomicAdd(&g_cnt[i2], 1);
    }
    float* ot = out + (size_t)gw * H_;
    for (int j = 0; j < H_ / 32; j++) {
        int h = j * 32 + lane;
        ot[h] = wid * xt[h];
    }
}

__global__ void k_offsets() {
    if (threadIdx.x != 0 || blockIdx.x != 0) return;
    for (int tt = 0; tt < NTILES; tt++) g_tileexp[tt] = -1;
    int o = 0;
    for (int e = 0; e < NROUTED; e++) {
        g_cur[e]    = o;
        g_segend[e] = o + g_cnt[e];
        int nt = (g_cnt[e] + BM - 1) / BM;
        for (int tt = 0; tt < nt; tt++) {
            int ti = o / BM + tt;
            if (ti < NTILES) g_tileexp[ti] = e;
        }
        o += nt * BM;
    }
}

__global__ void k_scatter() {
    int t = blockIdx.x * blockDim.x + threadIdx.x;
    if (t >= T_) return;
    for (int pqi = 0; pqi < 2; pqi++) {
        int e = g_top_e[2 * t + pqi];
        if (e < NROUTED) {
            int pos = atomicAdd(&g_cur[e], 1);
            g_tok[pos] = t;
            g_wt[pos]  = g_top_w[2 * t + pqi];
        }
    }
}

// ---------------------- K2: routed gate+up (gather, dual-B) ----------------
__global__ __launch_bounds__(256) void k2_gateup() {
    int e = g_tileexp[blockIdx.x];
    if (e < 0) return;
    int rbase  = blockIdx.x * BM;
    int nb     = blockIdx.y * BN;
    int segend = g_segend[e];
    const u16* wgh = g_wgTh + (size_t)e * I_ * H_;
    const u16* wgl = g_wgTl + (size_t)e * I_ * H_;
    const u16* wuh = g_wuTh + (size_t)e * I_ * H_;
    const u16* wul = g_wuTl + (size_t)e * I_ * H_;

    __shared__ __align__(16) u16 As_h[BM][AP], As_l[BM][AP];
    __shared__ __align__(16) u16 Bg_h[BN][AP], Bg_l[BN][AP];
    __shared__ __align__(16) u16 Bu_h[BN][AP], Bu_l[BN][AP];

    int tid = threadIdx.x;
    int wid = tid >> 5, lane = tid & 31;
    int gid = lane >> 2, tig = lane & 3;
    int wm = (wid & 3) * 32, wn = (wid >> 2) * 32;

    float dg[2][4][4] = {};
    float du[2][4][4] = {};

    int row0 = tid >> 2;               // A rows: row0, row0+64
    int kq   = (tid & 3) * 8;          // 8 u16 per 16B unit
    int bn0  = tid >> 2;               // B row (0..63)
    int tok0 = -1, tok1 = -1;
    {
        int r = rbase + row0;
        if (r < segend) tok0 = g_tok[r];
        r = rbase + row0 + 64;
        if (r < segend) tok1 = g_tok[r];
    }
    const uint4 z4 = make_uint4(0u, 0u, 0u, 0u);

    for (int ck = 0; ck < H_ / BKT; ck++) {
        int kk0 = ck * BKT;
        // A tile (gathered, pre-split)
        uint4 vh = z4, vl = z4;
        if (tok0 >= 0) {
            vh = *(const uint4*)&g_xh[(size_t)tok0 * H_ + kk0 + kq];
            vl = *(const uint4*)&g_xl[(size_t)tok0 * H_ + kk0 + kq];
        }
        *(uint4*)&As_h[row0][kq] = vh;
        *(uint4*)&As_l[row0][kq] = vl;
        vh = z4; vl = z4;
        if (tok1 >= 0) {
            vh = *(const uint4*)&g_xh[(size_t)tok1 * H_ + kk0 + kq];
            vl = *(const uint4*)&g_xl[(size_t)tok1 * H_ + kk0 + kq];
        }
        *(uint4*)&As_h[row0 + 64][kq] = vh;
        *(uint4*)&As_l[row0 + 64][kq] = vl;
        // B tiles (pre-transposed [n][k], pre-split): 1 unit per array per thread
        {
            size_t src = (size_t)(nb + bn0) * H_ + kk0 + kq;
            *(uint4*)&Bg_h[bn0][kq] = *(const uint4*)&wgh[src];
            *(uint4*)&Bg_l[bn0][kq] = *(const uint4*)&wgl[src];
            *(uint4*)&Bu_h[bn0][kq] = *(const uint4*)&wuh[src];
            *(uint4*)&Bu_l[bn0][kq] = *(const uint4*)&wul[src];
        }
        __syncthreads();
#pragma unroll
        for (int ks = 0; ks < 2; ks++) {
            int kc = ks * 16;
            unsigned ah[2][4], al[2][4];
#pragma unroll
            for (int mf = 0; mf < 2; mf++) {
                int m0 = wm + mf * 16;
                ah[mf][0] = *(const unsigned*)&As_h[m0 + gid][kc + 2 * tig];
                ah[mf][1] = *(const unsigned*)&As_h[m0 + gid + 8][kc + 2 * tig];
                ah[mf][2] = *(const unsigned*)&As_h[m0 + gid][kc + 2 * tig + 8];
                ah[mf][3] = *(const unsigned*)&As_h[m0 + gid + 8][kc + 2 * tig + 8];
                al[mf][0] = *(const unsigned*)&As_l[m0 + gid][kc + 2 * tig];
                al[mf][1] = *(const unsigned*)&As_l[m0 + gid + 8][kc + 2 * tig];
                al[mf][2] = *(const unsigned*)&As_l[m0 + gid][kc + 2 * tig + 8];
                al[mf][3] = *(const unsigned*)&As_l[m0 + gid + 8][kc + 2 * tig + 8];
            }
#pragma unroll
            for (int nf = 0; nf < 4; nf++) {
                int n0 = wn + nf * 8 + gid;
                unsigned bgh[2], bgl[2], buh[2], bul[2];
                bgh[0] = *(const unsigned*)&Bg_h[n0][kc + 2 * tig];
                bgh[1] = *(const unsigned*)&Bg_h[n0][kc + 2 * tig + 8];
                bgl[0] = *(const unsigned*)&Bg_l[n0][kc + 2 * tig];
                bgl[1] = *(const unsigned*)&Bg_l[n0][kc + 2 * tig + 8];
                buh[0] = *(const unsigned*)&Bu_h[n0][kc + 2 * tig];
                buh[1] = *(const unsigned*)&Bu_h[n0][kc + 2 * tig + 8];
                bul[0] = *(const unsigned*)&Bu_l[n0][kc + 2 * tig];
                bul[1] = *(const unsigned*)&Bu_l[n0][kc + 2 * tig + 8];
#pragma unroll
                for (int mf = 0; mf < 2; mf++) {
                    mma16816(dg[mf][nf], ah[mf], bgh);
                    mma16816(dg[mf][nf], al[mf], bgh);
                    mma16816(dg[mf][nf], ah[mf], bgl);
                    mma16816(du[mf][nf], ah[mf], buh);
                    mma16816(du[mf][nf], al[mf], buh);
                    mma16816(du[mf][nf], ah[mf], bul);
                }
            }
        }
        __syncthreads();
    }
    // epilogue: silu(g)*u, stored pre-split; zeros on padded rows
#pragma unroll
    for (int mf = 0; mf < 2; mf++)
#pragma unroll
        for (int nf = 0; nf < 4; nf++) {
            int n0 = nb + wn + nf * 8 + 2 * tig;
#pragma unroll
            for (int half = 0; half < 2; half++) {
                int r = rbase + wm + mf * 16 + gid + half * 8;
                float ox = 0.f, oy = 0.f;
                if (r < segend) {
                    ox = silu_f(dg[mf][nf][half * 2 + 0]) * du[mf][nf][half * 2 + 0];
                    oy = silu_f(dg[mf][nf][half * 2 + 1]) * du[mf][nf][half * 2 + 1];
                }
                u16 h0, l0, h1, l1;
                split2(ox, h0, l0); split2(oy, h1, l1);
                *(unsigned*)&g_hbh[(size_t)r * I_ + n0] = (unsigned)h0 | ((unsigned)h1 << 16);
                *(unsigned*)&g_hbl[(size_t)r * I_ + n0] = (unsigned)l0 | ((unsigned)l1 << 16);
            }
        }
}

// ---------------------- K3: routed down + weighted scatter -----------------
__global__ __launch_bounds__(256) void k3_down(float* __restrict__ out) {
    int e = g_tileexp[blockIdx.x];
    if (e < 0) return;
    int rbase  = blockIdx.x * BM;
    int nb     = blockIdx.y * BN;
    int segend = g_segend[e];
    const u16* wdh = g_wdTh + (size_t)e * H_ * I_;
    const u16* wdl = g_wdTl + (size_t)e * H_ * I_;

    __shared__ __align__(16) u16 As_h[BM][AP], As_l[BM][AP];
    __shared__ __align__(16) u16 Bs_h[BN][AP], Bs_l[BN][AP];

    int tid = threadIdx.x;
    int wid = tid >> 5, lane = tid & 31;
    int gid = lane >> 2, tig = lane & 3;
    int wm = (wid & 3) * 32, wn = (wid >> 2) * 32;

    float dd[2][4][4] = {};
    int row0 = tid >> 2;
    int kq   = (tid & 3) * 8;
    int bn0  = tid >> 2;

    for (int ck = 0; ck < I_ / BKT; ck++) {
        int kk0 = ck * BKT;
        {
            size_t s0 = (size_t)(rbase + row0) * I_ + kk0 + kq;
            size_t s1 = (size_t)(rbase + row0 + 64) * I_ + kk0 + kq;
            *(uint4*)&As_h[row0][kq]      = *(const uint4*)&g_hbh[s0];
            *(uint4*)&As_l[row0][kq]      = *(const uint4*)&g_hbl[s0];
            *(uint4*)&As_h[row0 + 64][kq] = *(const uint4*)&g_hbh[s1];
            *(uint4*)&As_l[row0 + 64][kq] = *(const uint4*)&g_hbl[s1];
            size_t sb = (size_t)(nb + bn0) * I_ + kk0 + kq;
            *(uint4*)&Bs_h[bn0][kq] = *(const uint4*)&wdh[sb];
            *(uint4*)&Bs_l[bn0][kq] = *(const uint4*)&wdl[sb];
        }
        __syncthreads();
#pragma unroll
        for (int ks = 0; ks < 2; ks++) {
            int kc = ks * 16;
            unsigned ah[2][4], al[2][4];
#pragma unroll
            for (int mf = 0; mf < 2; mf++) {
                int m0 = wm + mf * 16;
                ah[mf][0] = *(const unsigned*)&As_h[m0 + gid][kc + 2 * tig];
                ah[mf][1] = *(const unsigned*)&As_h[m0 + gid + 8][kc + 2 * tig];
                ah[mf][2] = *(const unsigned*)&As_h[m0 + gid][kc + 2 * tig + 8];
                ah[mf][3] = *(const unsigned*)&As_h[m0 + gid + 8][kc + 2 * tig + 8];
                al[mf][0] = *(const unsigned*)&As_l[m0 + gid][kc + 2 * tig];
                al[mf][1] = *(const unsigned*)&As_l[m0 + gid + 8][kc + 2 * tig];
                al[mf][2] = *(const unsigned*)&As_l[m0 + gid][kc + 2 * tig + 8];
                al[mf][3] = *(const unsigned*)&As_l[m0 + gid + 8][kc + 2 * tig + 8];
            }
#pragma unroll
            for (int nf = 0; nf < 4; nf++) {
                int n0 = wn + nf * 8 + gid;
                unsigned bh[2], bl[2];
                bh[0] = *(const unsigned*)&Bs_h[n0][kc + 2 * tig];
                bh[1] = *(const unsigned*)&Bs_h[n0][kc + 2 * tig + 8];
                bl[0] = *(const unsigned*)&Bs_l[n0][kc + 2 * tig];
                bl[1] = *(const unsigned*)&Bs_l[n0][kc + 2 * tig + 8];
#pragma unroll
                for (int mf = 0; mf < 2; mf++) {
                    mma16816(dd[mf][nf], ah[mf], bh);
                    mma16816(dd[mf][nf], al[mf], bh);
                    mma16816(dd[mf][nf], ah[mf], bl);
                }
            }
        }
        __syncthreads();
    }
#pragma unroll
    for (int mf = 0; mf < 2; mf++)
#pragma unroll
        for (int half = 0; half < 2; half++) {
            int r = rbase + wm + mf * 16 + gid + half * 8;
            if (r < segend) {
                int tt = g_tok[r];
                float w = g_wt[r];
                float* op = out + (size_t)tt * H_;
#pragma unroll
                for (int nf = 0; nf < 4; nf++) {
                    int n0 = nb + wn + nf * 8 + 2 * tig;
                    atomicAdd(op + n0,     w * dd[mf][nf][half * 2 + 0]);
                    atomicAdd(op + n0 + 1, w * dd[mf][nf][half * 2 + 1]);
                }
            }
        }
}

// -------------- K4: shared conv-gate (3 shifted GEMMs) + up, fused ---------
__global__ __launch_bounds__(256) void k4_shared_gateup() {
    int mb = blockIdx.x * BM;
    int nb = blockIdx.y * BN;

    __shared__ __align__(16) u16 As_h[BM][AP], As_l[BM][AP];
    __shared__ __align__(16) u16 Bs_h[BN][AP], Bs_l[BN][AP];

    int tid = threadIdx.x;
    int wid = tid >> 5, lane = tid & 31;
    int gid = lane >> 2, tig = lane & 3;
    int wm = (wid & 3) * 32, wn = (wid >> 2) * 32;

    float dg[2][4][4] = {};
    float du[2][4][4] = {};
    int row0 = tid >> 2;
    int kq   = (tid & 3) * 8;
    int bn0  = tid >> 2;
    const uint4 z4 = make_uint4(0u, 0u, 0u, 0u);

#pragma unroll 1
    for (int ck = 0; ck < 4 * (H_ / BKT); ck++) {
        int grp = ck >> 5;                 // 0,1,2: conv taps (shift 2,1,0); 3: up
        int kk0 = (ck & 31) * BKT;
        int d = (grp == 0) ? 2 : ((grp == 1) ? 1 : 0);
        const u16* bh = (grp < 3) ? (g_cth + (size_t)grp * I_ * H_) : g_supTh;
        const u16* bl = (grp < 3) ? (g_ctl + (size_t)grp * I_ * H_) : g_supTl;
#pragma unroll
        for (int i = 0; i < 2; i++) {
            int ml = row0 + i * 64;
            int gm = mb + ml;
            uint4 vh = z4, vl = z4;
            if ((gm & (S_ - 1)) >= d) {
                vh = *(const uint4*)&g_xh[(size_t)(gm - d) * H_ + kk0 + kq];
                vl = *(const uint4*)&g_xl[(size_t)(gm - d) * H_ + kk0 + kq];
            }
            *(uint4*)&As_h[ml][kq] = vh;
            *(uint4*)&As_l[ml][kq] = vl;
        }
        {
            size_t sb = (size_t)(nb + bn0) * H_ + kk0 + kq;
            *(uint4*)&Bs_h[bn0][kq] = *(const uint4*)&bh[sb];
            *(uint4*)&Bs_l[bn0][kq] = *(const uint4*)&bl[sb];
        }
        __syncthreads();
#pragma unroll
        for (int ks = 0; ks < 2; ks++) {
            int kc = ks * 16;
            unsigned ah[2][4], al[2][4];
#pragma unroll
            for (int mf = 0; mf < 2; mf++) {
                int m0 = wm + mf * 16;
                ah[mf][0] = *(const unsigned*)&As_h[m0 + gid][kc + 2 * tig];
                ah[mf][1] = *(const unsigned*)&As_h[m0 + gid + 8][kc + 2 * tig];
                ah[mf][2] = *(const unsigned*)&As_h[m0 + gid][kc + 2 * tig + 8];
                ah[mf][3] = *(const unsigned*)&As_h[m0 + gid + 8][kc + 2 * tig + 8];
                al[mf][0] = *(const unsigned*)&As_l[m0 + gid][kc + 2 * tig];
                al[mf][1] = *(const unsigned*)&As_l[m0 + gid + 8][kc + 2 * tig];
                al[mf][2] = *(const unsigned*)&As_l[m0 + gid][kc + 2 * tig + 8];
                al[mf][3] = *(const unsigned*)&As_l[m0 + gid + 8][kc + 2 * tig + 8];
            }
#pragma unroll
            for (int nf = 0; nf < 4; nf++) {
                int n0 = wn + nf * 8 + gid;
                unsigned bfh[2], bfl[2];
                bfh[0] = *(const unsigned*)&Bs_h[n0][kc + 2 * tig];
                bfh[1] = *(const unsigned*)&Bs_h[n0][kc + 2 * tig + 8];
                bfl[0] = *(const unsigned*)&Bs_l[n0][kc + 2 * tig];
                bfl[1] = *(const unsigned*)&Bs_l[n0][kc + 2 * tig + 8];
                if (grp < 3) {
#pragma unroll
                    for (int mf = 0; mf < 2; mf++) {
                        mma16816(dg[mf][nf], ah[mf], bfh);
                        mma16816(dg[mf][nf], al[mf], bfh);
                        mma16816(dg[mf][nf], ah[mf], bfl);
                    }
                } else {
#pragma unroll
                    for (int mf = 0; mf < 2; mf++) {
                        mma16816(du[mf][nf], ah[mf], bfh);
                        mma16816(du[mf][nf], al[mf], bfh);
                        mma16816(du[mf][nf], ah[mf], bfl);
                    }
                }
            }
        }
        __syncthreads();
    }
#pragma unroll
    for (int mf = 0; mf < 2; mf++)
#pragma unroll
        for (int nf = 0; nf < 4; nf++) {
            int n0 = nb + wn + nf * 8 + 2 * tig;
#pragma unroll
            for (int half = 0; half < 2; half++) {
                int m = mb + wm + mf * 16 + gid + half * 8;
                float ox = silu_f(dg[mf][nf][half * 2 + 0]) * du[mf][nf][half * 2 + 0];
                float oy = silu_f(dg[mf][nf][half * 2 + 1]) * du[mf][nf][half * 2 + 1];
                u16 h0, l0, h1, l1;
                split2(ox, h0, l0); split2(oy, h1, l1);
                *(unsigned*)&g_shh[(size_t)m * I_ + n0] = (unsigned)h0 | ((unsigned)h1 << 16);
                *(unsigned*)&g_shl[(size_t)m * I_ + n0] = (unsigned)l0 | ((unsigned)l1 << 16);
            }
        }
}

// ---------------------- K5: shared down, out += ----------------------------
__global__ __launch_bounds__(256) void k5_shared_down(float* __restrict__ out) {
    int mb = blockIdx.x * BM;
    int nb = blockIdx.y * BN;

    __shared__ __align__(16) u16 As_h[BM][AP], As_l[BM][AP];
    __shared__ __align__(16) u16 Bs_h[BN][AP], Bs_l[BN][AP];

    int tid = threadIdx.x;
    int wid = tid >> 5, lane = tid & 31;
    int gid = lane >> 2, tig = lane & 3;
    int wm = (wid & 3) * 32, wn = (wid >> 2) * 32;

    float dd[2][4][4] = {};
    int row0 = tid >> 2;
    int kq   = (tid & 3) * 8;
    int bn0  = tid >> 2;

    for (int ck = 0; ck < I_ / BKT; ck++) {
        int kk0 = ck * BKT;
        {
            size_t s0 = (size_t)(mb + row0) * I_ + kk0 + kq;
            size_t s1 = (size_t)(mb + row0 + 64) * I_ + kk0 + kq;
            *(uint4*)&As_h[row0][kq]      = *(const uint4*)&g_shh[s0];
            *(uint4*)&As_l[row0][kq]      = *(const uint4*)&g_shl[s0];
            *(uint4*)&As_h[row0 + 64][kq] = *(const uint4*)&g_shh[s1];
            *(uint4*)&As_l[row0 + 64][kq] = *(const uint4*)&g_shl[s1];
            size_t sb = (size_t)(nb + bn0) * I_ + kk0 + kq;
            *(uint4*)&Bs_h[bn0][kq] = *(const uint4*)&g_sdnTh[sb];
            *(uint4*)&Bs_l[bn0][kq] = *(const uint4*)&g_sdnTl[sb];
        }
        __syncthreads();
#pragma unroll
        for (int ks = 0; ks < 2; ks++) {
            int kc = ks * 16;
            unsigned ah[2][4], al[2][4];
#pragma unroll
            for (int mf = 0; mf < 2; mf++) {
                int m0 = wm + mf * 16;
                ah[mf][0] = *(const unsigned*)&As_h[m0 + gid][kc + 2 * tig];
                ah[mf][1] = *(const unsigned*)&As_h[m0 + gid + 8][kc + 2 * tig];
                ah[mf][2] = *(const unsigned*)&As_h[m0 + gid][kc + 2 * tig + 8];
                ah[mf][3] = *(const unsigned*)&As_h[m0 + gid + 8][kc + 2 * tig + 8];
                al[mf][0] = *(const unsigned*)&As_l[m0 + gid][kc + 2 * tig];
                al[mf][1] = *(const unsigned*)&As_l[m0 + gid + 8][kc + 2 * tig];
                al[mf][2] = *(const unsigned*)&As_l[m0 + gid][kc + 2 * tig + 8];
                al[mf][3] = *(const unsigned*)&As_l[m0 + gid + 8][kc + 2 * tig + 8];
            }
#pragma unroll
            for (int nf = 0; nf < 4; nf++) {
                int n0 = wn + nf * 8 + gid;
                unsigned bh[2], bl[2];
                bh[0] = *(const unsigned*)&Bs_h[n0][kc + 2 * tig];
                bh[1] = *(const unsigned*)&Bs_h[n0][kc + 2 * tig + 8];
                bl[0] = *(const unsigned*)&Bs_l[n0][kc + 2 * tig];
                bl[1] = *(const unsigned*)&Bs_l[n0][kc + 2 * tig + 8];
#pragma unroll
                for (int mf = 0; mf < 2; mf++) {
                    mma16816(dd[mf][nf], ah[mf], bh);
                    mma16816(dd[mf][nf], al[mf], bh);
                    mma16816(dd[mf][nf], ah[mf], bl);
                }
            }
        }
        __syncthreads();
    }
#pragma unroll
    for (int mf = 0; mf < 2; mf++)
#pragma unroll
        for (int nf = 0; nf < 4; nf++) {
            int n0 = nb + wn + nf * 8 + 2 * tig;
#pragma unroll
            for (int half = 0; half < 2; half++) {
                int m = mb + wm + mf * 16 + gid + half * 8;
                float* op = out + (size_t)m * H_ + n0;
                float2 o = *(const float2*)op;
                o.x += dd[mf][nf][half * 2 + 0];
                o.y += dd[mf][nf][half * 2 + 1];
                *(float2*)op = o;
            }
        }
}

// ------------------------------- launcher ----------------------------------
extern "C" void kernel_launch(void* const* d_in, const int* in_sizes, int n_in,
                              void* d_out, int out_size) {
    const float* x   = (const float*)d_in[0];
    const float* rw  = (const float*)d_in[1];
    const float* rb  = (const float*)d_in[2];
    const float* wg  = (const float*)d_in[3];
    const float* wu  = (const float*)d_in[4];
    const float* wd  = (const float*)d_in[5];
    const float* cw  = (const float*)d_in[6];
    const float* sup = (const float*)d_in[7];
    const float* sdn = (const float*)d_in[8];
    float* out = (float*)d_out;

    dim3 tb(32, 8);
    // prep: split + transpose everything once (outputs selected device-side)
    k_split_x<<<(T_ * H_ / 4 + 255) / 256, 256>>>(x);
    k_prep_conv<<<(KS_ * I_ * H_ + 255) / 256, 256>>>(cw);
    k_tsplit<<<dim3(I_ / 32, H_ / 32, NROUTED), tb>>>(wg,  0, H_, I_);
    k_tsplit<<<dim3(I_ / 32, H_ / 32, NROUTED), tb>>>(wu,  1, H_, I_);
    k_tsplit<<<dim3(H_ / 32, I_ / 32, NROUTED), tb>>>(wd,  2, I_, H_);
    k_tsplit<<<dim3(I_ / 32, H_ / 32, 1),       tb>>>(sup, 3, H_, I_);
    k_tsplit<<<dim3(H_ / 32, I_ / 32, 1),       tb>>>(sdn, 4, I_, H_);
    // routing
    k_router<<<T_ / 8, 256>>>(x, rw, rb, out);
    k_offsets<<<1, 1>>>();
    k_scatter<<<(T_ + 255) / 256, 256>>>();
    // GEMMs
    k2_gateup<<<dim3(NTILES, I_ / BN), 256>>>();
    k3_down<<<dim3(NTILES, H_ / BN), 256>>>(out);
    k4_shared_gateup<<<dim3(T_ / BM, I_ / BN), 256>>>();
    k5_shared_down<<<dim3(T_ / BM, H_ / BN), 256>>>(out);
}